// round 5
// baseline (speedup 1.0000x reference)
#include <cuda_runtime.h>
#include <cuda_bf16.h>
#include <cstdint>

#define BATCH 2
#define NBOX  20000
#define CH    256
#define KTOP  5000
#define KP    5120
#define NLAYERS 6
#define CANDMAX 8192
#define SEGLEN 2048

// ---------------- scratch (no allocations allowed) ----------------
__device__ unsigned long long g_cand[BATCH * CANDMAX];
__device__ int            g_thrb[BATCH];
__device__ int            g_cnt[BATCH];
__device__ int            g_rank[BATCH * CANDMAX];
__device__ int            g_keep[BATCH * KTOP];
__device__ float4         g_boxk[BATCH * KTOP];
__device__ float          g_areak[BATCH * KTOP];
__device__ unsigned int   g_flags[BATCH * KTOP];
__device__ __nv_bfloat16  g_xb0[BATCH * KP * CH];
__device__ __nv_bfloat16  g_xb1[BATCH * KP * CH];
__device__ __nv_bfloat16  g_Wbf[NLAYERS * CH * CH];

__device__ __forceinline__ uint32_t smem_u32(const void* p) {
    uint32_t a;
    asm("{ .reg .u64 t; cvta.to.shared.u64 t, %1; cvt.u32.u64 %0, t; }" : "=r"(a) : "l"(p));
    return a;
}

// ---------------- 0) convert W to bf16 ----------------
__global__ void k_prep(const float* __restrict__ W) {
    int i = blockIdx.x * blockDim.x + threadIdx.x;
    if (i < NLAYERS * CH * CH) g_Wbf[i] = __float2bfloat16_rn(W[i]);
}

// ---------------- 1) top-K selection: histogram + threshold bucket ----------------
// scores are positive floats -> bucket = bits>>19 is monotone in score.
__global__ void s1_hist(const float* __restrict__ score) {
    __shared__ uint32_t hist[8192];
    __shared__ uint32_t part[1024];
    int b = blockIdx.x, tid = threadIdx.x;
#pragma unroll
    for (int q = 0; q < 8; q++) hist[tid + q * 1024] = 0;
    __syncthreads();
    for (int n = tid; n < NBOX; n += 1024) {
        unsigned bits = __float_as_uint(score[b * NBOX + n]);
        atomicAdd(&hist[bits >> 19], 1u);
    }
    __syncthreads();
    uint32_t cs = 0;
#pragma unroll
    for (int q = 7; q >= 0; q--) cs += hist[tid * 8 + q];
    part[tid] = cs;
    __syncthreads();
    for (int off = 1; off < 1024; off <<= 1) {
        uint32_t v = part[tid] + ((tid + off < 1024) ? part[tid + off] : 0u);
        __syncthreads();
        part[tid] = v;
        __syncthreads();
    }
    uint32_t s = (tid < 1023) ? part[tid + 1] : 0u;   // elems in buckets above this chunk
#pragma unroll
    for (int q = 7; q >= 0; q--) {
        uint32_t ns = s + hist[tid * 8 + q];
        if (s < (uint32_t)KTOP && ns >= (uint32_t)KTOP) g_thrb[b] = tid * 8 + q;
        s = ns;
    }
    if (tid == 0) g_cnt[b] = 0;
}

// ---------------- 2) candidate compaction (also zeroes g_rank) ----------------
__global__ void s2_collect(const float* __restrict__ score) {
    int i = blockIdx.x * blockDim.x + threadIdx.x;
    if (i < BATCH * CANDMAX) g_rank[i] = 0;
    if (i >= BATCH * NBOX) return;
    int b = i / NBOX, n = i - b * NBOX;
    unsigned bits = __float_as_uint(score[b * NBOX + n]);
    if ((int)(bits >> 19) >= g_thrb[b]) {
        int pos = atomicAdd(&g_cnt[b], 1);
        if (pos < CANDMAX)
            g_cand[b * CANDMAX + pos] =
                ((unsigned long long)bits << 32) | (0xFFFFFFFFu - (unsigned)n);
    }
}

// ---------------- 3) exact rank = count of strictly-greater keys ----------------
__global__ void s3_rank() {
    __shared__ unsigned long long sk[SEGLEN];
    int b = blockIdx.z;
    int cnt = min(g_cnt[b], CANDMAX);
    int seg0 = blockIdx.x * SEGLEN;
    if (seg0 >= cnt) return;
    int tid = threadIdx.x;
    int lim = min(SEGLEN, cnt - seg0);
    for (int q = tid; q < SEGLEN; q += 256)
        sk[q] = (seg0 + q < cnt) ? g_cand[b * CANDMAX + seg0 + q] : 0ull;
    __syncthreads();
    int t = blockIdx.y * 256 + tid;
    if (t >= cnt) return;
    unsigned long long my = g_cand[b * CANDMAX + t];
    int r = 0;
#pragma unroll 4
    for (int q = 0; q < lim; q++) r += (sk[q] > my) ? 1 : 0;
    if (r) atomicAdd(&g_rank[b * CANDMAX + t], r);
}

// ---------------- 4) scatter top-K by rank (replaces extract) ----------------
__global__ void s4_scatter(const float* __restrict__ box, float* __restrict__ out,
                           int write_keep) {
    int b = blockIdx.y;
    int t = blockIdx.x * blockDim.x + threadIdx.x;
    int cnt = min(g_cnt[b], CANDMAX);
    if (t >= cnt) return;
    int r = g_rank[b * CANDMAX + t];
    if (r >= KTOP) return;
    unsigned long long key = g_cand[b * CANDMAX + t];
    int idx = (int)(0xFFFFFFFFu - (unsigned)(key & 0xFFFFFFFFull));
    g_keep[b * KTOP + r] = idx;
    g_flags[b * KTOP + r] = 0u;
    const float* bb = box + b * 4 * NBOX;
    float x1 = bb[idx], y1 = bb[NBOX + idx], x2 = bb[2 * NBOX + idx], y2 = bb[3 * NBOX + idx];
    g_boxk[b * KTOP + r] = make_float4(x1, y1, x2, y2);
    g_areak[b * KTOP + r] = (x2 - x1) * (y2 - y1);
    if (write_keep) out[BATCH * KTOP + b * KTOP + r] = (float)idx;
}

// ---------------- gather: token-major bf16, one warp per token ----------------
__global__ void k_gather(const float* __restrict__ feat) {
    int w = (blockIdx.x * blockDim.x + threadIdx.x) >> 5;
    int lane = threadIdx.x & 31;
    if (w >= BATCH * KP) return;
    int b = w / KP, t = w - b * KP;
    uint4* dst = (uint4*)(g_xb0 + (size_t)w * CH);
    if (t >= KTOP) { dst[lane] = make_uint4(0, 0, 0, 0); return; }
    int idx = g_keep[b * KTOP + t];
    const float* f = feat + (size_t)b * CH * NBOX + idx;
    __nv_bfloat16 h[8];
#pragma unroll
    for (int q = 0; q < 8; q++)
        h[q] = __float2bfloat16_rn(f[(size_t)(lane * 8 + q) * NBOX]);
    dst[lane] = *(uint4*)h;
}

// ---------------- IoU local-max flags (division-free) ----------------
__global__ void k_iou() {
    int ti = blockIdx.x, tj = blockIdx.y, b = blockIdx.z;
    if (ti > tj) return;
    __shared__ float4 sbx[128];
    __shared__ float  sar[128];
    int tid = threadIdx.x;
    int gi0 = ti * 128;
    int gl = gi0 + tid;
    if (gl < KTOP) { sbx[tid] = g_boxk[b * KTOP + gl]; sar[tid] = g_areak[b * KTOP + gl]; }
    __syncthreads();
    int j = tj * 128 + tid;
    if (j >= KTOP) return;
    float4 bj = g_boxk[b * KTOP + j];
    float  aj = g_areak[b * KTOP + j];
    int imax = min(KTOP, min(j, gi0 + 128)) - gi0;
    unsigned int fl = 0u;
    for (int i = 0; i < imax; i++) {
        float4 bi = sbx[i];
        float w = fminf(bi.z, bj.z) - fmaxf(bi.x, bj.x);
        float h = fminf(bi.w, bj.w) - fmaxf(bi.y, bj.y);
        w = fmaxf(w, 0.f); h = fmaxf(h, 0.f);
        float inter = w * h;
        float uni = sar[i] + aj - inter;
        if (inter >= 0.4f * uni) fl |= 1u;
        if (inter >= 0.6f * uni) fl |= 2u;
        if (inter >= 0.8f * uni) fl |= 4u;
        if (fl == 7u) break;
    }
    if (fl) atomicOr(&g_flags[b * KTOP + j], fl);
}

// ---------------- bf16 mma.sync layer ----------------
#define ROWB   528
#define TILEB  (128 * ROWB)
#define SMEM_GEMM (2 * TILEB + 512)

__device__ __forceinline__ void ldm4(uint32_t* r, uint32_t addr) {
    asm volatile("ldmatrix.sync.aligned.m8n8.x4.shared.b16 {%0,%1,%2,%3}, [%4];"
                 : "=r"(r[0]), "=r"(r[1]), "=r"(r[2]), "=r"(r[3]) : "r"(addr));
}
__device__ __forceinline__ void mma16816(float* c, const uint32_t* a,
                                         uint32_t b0, uint32_t b1) {
    asm volatile(
        "mma.sync.aligned.m16n8k16.row.col.f32.bf16.bf16.f32 "
        "{%0,%1,%2,%3}, {%4,%5,%6,%7}, {%8,%9}, {%0,%1,%2,%3};"
        : "+f"(c[0]), "+f"(c[1]), "+f"(c[2]), "+f"(c[3])
        : "r"(a[0]), "r"(a[1]), "r"(a[2]), "r"(a[3]), "r"(b0), "r"(b1));
}

__global__ void __launch_bounds__(256, 1)
k_mma(const __nv_bfloat16* __restrict__ Xin, __nv_bfloat16* __restrict__ Yout,
      int layer, const float* __restrict__ bvec) {
    extern __shared__ char smem[];
    float* sbias = (float*)(smem + 2 * TILEB);
    uint32_t sx = smem_u32(smem);
    uint32_t sw = sx + TILEB;
    int tid = threadIdx.x, wid = tid >> 5, lane = tid & 31;
    int bx = blockIdx.x, by = blockIdx.y, bz = blockIdx.z;

    const uint4* gX = (const uint4*)(Xin + ((size_t)bz * KP + (size_t)bx * 128) * CH);
    const uint4* gW = (const uint4*)(g_Wbf + (size_t)layer * CH * CH + (size_t)by * 128 * CH);
#pragma unroll
    for (int it = 0; it < 16; it++) {
        int c = tid + it * 256;
        int row = c >> 5, ch = (c & 31) * 8;
        *(uint4*)(smem + row * ROWB + ch * 2)         = gX[c];
        *(uint4*)(smem + TILEB + row * ROWB + ch * 2) = gW[c];
    }
    if (tid < 128) sbias[tid] = bvec[layer * CH + by * 128 + tid];
    __syncthreads();

    int wm = wid & 3, wn = wid >> 2;
    float acc[2][8][4];
#pragma unroll
    for (int i = 0; i < 2; i++)
#pragma unroll
        for (int j = 0; j < 8; j++)
#pragma unroll
            for (int q = 0; q < 4; q++) acc[i][j][q] = 0.f;

    int a_row  = lane & 15;
    int a_koff = (lane >> 4) * 8;
    int b_row  = (lane & 7) + ((lane >> 4) << 3);
    int b_koff = ((lane >> 3) & 1) * 8;
    uint32_t xbase = sx + (uint32_t)(wm * 32) * ROWB;
    uint32_t wbase = sw + (uint32_t)(wn * 64) * ROWB;

#pragma unroll 4
    for (int kk = 0; kk < 256; kk += 16) {
        uint32_t a[2][4];
#pragma unroll
        for (int mi = 0; mi < 2; mi++)
            ldm4(a[mi], xbase + (uint32_t)(mi * 16 + a_row) * ROWB + (kk + a_koff) * 2);
        uint32_t bfr[4][4];
#pragma unroll
        for (int ni = 0; ni < 4; ni++)
            ldm4(bfr[ni], wbase + (uint32_t)(ni * 16 + b_row) * ROWB + (kk + b_koff) * 2);
#pragma unroll
        for (int mi = 0; mi < 2; mi++)
#pragma unroll
            for (int nj = 0; nj < 8; nj++)
                mma16816(acc[mi][nj], a[mi], bfr[nj >> 1][(nj & 1) * 2],
                         bfr[nj >> 1][(nj & 1) * 2 + 1]);
    }

    int tq = lane >> 2, tr = lane & 3;
    __nv_bfloat16* Yb = Yout + ((size_t)bz * KP + (size_t)bx * 128) * CH + (size_t)by * 128;
#pragma unroll
    for (int mi = 0; mi < 2; mi++) {
#pragma unroll
        for (int nj = 0; nj < 8; nj++) {
            int n = wn * 64 + nj * 8 + tr * 2;
            float b0v = sbias[n], b1v = sbias[n + 1];
            int m0 = wm * 32 + mi * 16 + tq;
#pragma unroll
            for (int h = 0; h < 2; h++) {
                float v0 = acc[mi][nj][h * 2 + 0] + b0v;
                float v1 = acc[mi][nj][h * 2 + 1] + b1v;
                v0 = v0 > 0.f ? v0 : 0.2f * v0;
                v1 = v1 > 0.f ? v1 : 0.2f * v1;
                __nv_bfloat162 pk;
                pk.x = __float2bfloat16_rn(v0);
                pk.y = __float2bfloat16_rn(v1);
                *(__nv_bfloat162*)(Yb + (size_t)(m0 + h * 8) * CH + n) = pk;
            }
        }
    }
}

// ---------------- final head: warp per token ----------------
__global__ void k_final(const float* __restrict__ Wf, const float* __restrict__ bf,
                        float* __restrict__ out) {
    int w = (blockIdx.x * blockDim.x + threadIdx.x) >> 5;
    int lane = threadIdx.x & 31;
    if (w >= BATCH * KTOP) return;
    int b = w / KTOP, t = w - b * KTOP;
    const uint4* x = (const uint4*)(g_xb0 + ((size_t)b * KP + t) * CH);
    uint4 raw = x[lane];
    __nv_bfloat16 h[8];
    *(uint4*)h = raw;
    float l0 = 0.f, l1 = 0.f, l2 = 0.f;
    int c0 = lane * 8;
#pragma unroll
    for (int q = 0; q < 8; q++) {
        float xv = __bfloat162float(h[q]);
        l0 += Wf[c0 + q] * xv;
        l1 += Wf[CH + c0 + q] * xv;
        l2 += Wf[2 * CH + c0 + q] * xv;
    }
#pragma unroll
    for (int o = 16; o; o >>= 1) {
        l0 += __shfl_xor_sync(0xFFFFFFFFu, l0, o);
        l1 += __shfl_xor_sync(0xFFFFFFFFu, l1, o);
        l2 += __shfl_xor_sync(0xFFFFFFFFu, l2, o);
    }
    if (lane == 0) {
        l0 += bf[0]; l1 += bf[1]; l2 += bf[2];
        float m = fmaxf(l0, fmaxf(l1, l2));
        float e0 = expf(l0 - m), e1 = expf(l1 - m), e2 = expf(l2 - m);
        float inv = 1.f / (e0 + e1 + e2);
        unsigned int fl = g_flags[b * KTOP + t];
        float loc = 0.f;
        if (!(fl & 1u)) loc += e0 * inv;
        if (!(fl & 2u)) loc += e1 * inv;
        if (!(fl & 4u)) loc += e2 * inv;
        out[b * KTOP + t] = loc;
    }
}

// ---------------- launch ----------------
extern "C" void kernel_launch(void* const* d_in, const int* in_sizes, int n_in,
                              void* d_out, int out_size) {
    const float* box   = (const float*)d_in[0];
    const float* score = (const float*)d_in[1];
    const float* feat  = (const float*)d_in[2];
    const float* W     = (const float*)d_in[3];
    const float* bvec  = (const float*)d_in[4];
    const float* Wf    = (const float*)d_in[5];
    const float* bf    = (const float*)d_in[6];
    float* out = (float*)d_out;
    int write_keep = (out_size >= 2 * BATCH * KTOP) ? 1 : 0;

    static int init_done = 0;
    static __nv_bfloat16 *x0p = nullptr, *x1p = nullptr;
    if (!init_done) {
        cudaFuncSetAttribute(k_mma, cudaFuncAttributeMaxDynamicSharedMemorySize, SMEM_GEMM);
        cudaGetSymbolAddress((void**)&x0p, g_xb0);
        cudaGetSymbolAddress((void**)&x1p, g_xb1);
        init_done = 1;
    }

    k_prep<<<(NLAYERS * CH * CH + 255) / 256, 256>>>(W);
    s1_hist<<<BATCH, 1024>>>(score);
    s2_collect<<<(BATCH * NBOX + 255) / 256, 256>>>(score);
    s3_rank<<<dim3(CANDMAX / SEGLEN, CANDMAX / 256, BATCH), 256>>>();
    s4_scatter<<<dim3(CANDMAX / 256, BATCH), 256>>>(box, out, write_keep);
    k_gather<<<BATCH * KP / 8, 256>>>(feat);
    k_iou<<<dim3(40, 40, BATCH), 128>>>();
    for (int l = 0; l < NLAYERS; l++) {
        const __nv_bfloat16* Xi = (l & 1) ? x1p : x0p;
        __nv_bfloat16*       Yo = (l & 1) ? x0p : x1p;
        k_mma<<<dim3(KP / 128, 2, BATCH), 256, SMEM_GEMM>>>(Xi, Yo, l, bvec);
    }
    k_final<<<(BATCH * KTOP + 7) / 8, 256>>>(Wf, bf, out);
}